// round 5
// baseline (speedup 1.0000x reference)
#include <cuda_runtime.h>

#define HH 64
#define WW 64
#define NB 8
#define C1 256
#define C2 256
#define KK 9
#define HWSZ 4096
#define CK 2304  /* C1*KK */

// Scratch (allocation-free rule: __device__ globals)
__device__ float g_offmod[NB * 27 * HWSZ];                 // 3.5 MB: 18 clipped offsets + 9 sigmoids
__device__ float g_col[(size_t)NB * CK * HWSZ];            // 302 MB im2col-with-sampling tensor

// ---------------------------------------------------------------------------
// Kernel 1: fused offset+modulator 3x3 conv (27 output channels).
// Block = 16x16 threads = one 16x16 pixel tile; loop channels in chunks of 8.
// ---------------------------------------------------------------------------
#define CH 8
__global__ __launch_bounds__(256) void offmod_kernel(
    const float* __restrict__ x,
    const float* __restrict__ ow, const float* __restrict__ ob,
    const float* __restrict__ mw, const float* __restrict__ mb)
{
    __shared__ float sx[CH][18 * 18];
    __shared__ float sw[27][CH * 9];
    const int b   = blockIdx.z;
    const int ty0 = blockIdx.y * 16, tx0 = blockIdx.x * 16;
    const int tx  = threadIdx.x, ty = threadIdx.y;
    const int tid = ty * 16 + tx;

    float acc[27];
#pragma unroll
    for (int i = 0; i < 18; i++) acc[i] = ob[i];
#pragma unroll
    for (int i = 0; i < 9; i++)  acc[18 + i] = mb[i];

    for (int c0 = 0; c0 < C1; c0 += CH) {
        __syncthreads();
        // load x tile (with 1-pixel halo, zero padded)
        for (int i = tid; i < CH * 324; i += 256) {
            int c = i / 324, r = i % 324;
            int yy = r / 18 - 1 + ty0;
            int xx = r % 18 - 1 + tx0;
            float v = 0.f;
            if ((unsigned)yy < 64u && (unsigned)xx < 64u)
                v = x[(((b * C1) + c0 + c) * HH + yy) * WW + xx];
            sx[c][r] = v;
        }
        // load weight chunk: 27 x CH x 9
        for (int i = tid; i < 27 * CH * 9; i += 256) {
            int oc = i / (CH * 9), r = i % (CH * 9);
            int c = r / 9, k = r % 9;
            sw[oc][r] = (oc < 18) ? ow[(oc * C1 + c0 + c) * 9 + k]
                                  : mw[((oc - 18) * C1 + c0 + c) * 9 + k];
        }
        __syncthreads();
#pragma unroll
        for (int c = 0; c < CH; c++) {
            float xv[9];
#pragma unroll
            for (int k = 0; k < 9; k++)
                xv[k] = sx[c][(ty + k / 3) * 18 + (tx + k % 3)];
#pragma unroll
            for (int oc = 0; oc < 27; oc++) {
#pragma unroll
                for (int k = 0; k < 9; k++)
                    acc[oc] = fmaf(xv[k], sw[oc][c * 9 + k], acc[oc]);
            }
        }
    }

    const int p = (ty0 + ty) * WW + (tx0 + tx);
#pragma unroll
    for (int oc = 0; oc < 27; oc++) {
        float v = acc[oc];
        if (oc < 18) v = fminf(fmaxf(v, -16.f), 16.f);        // max_offset = 64/4
        else         v = 1.f / (1.f + expf(-v));              // sigmoid
        g_offmod[(b * 27 + oc) * HWSZ + p] = v;
    }
}

// ---------------------------------------------------------------------------
// Kernel 2: bilinear sampling + modulation -> column tensor
// One thread per (b, kk, ho, wo); loops over all 256 channels.
// col layout: [b][c*9+kk][hw]  (matches weight.reshape(C2, C*KK))
// ---------------------------------------------------------------------------
__global__ __launch_bounds__(256) void sample_kernel(const float* __restrict__ x)
{
    int t  = blockIdx.x * 256 + threadIdx.x;
    int wo = t & 63;
    int ho = (t >> 6) & 63;
    int r  = t >> 12;
    int kk = r % 9;
    int b  = r / 9;
    int p  = ho * WW + wo;

    const float* om = g_offmod + b * 27 * HWSZ;
    float dy = om[(2 * kk) * HWSZ + p];
    float dx = om[(2 * kk + 1) * HWSZ + p];
    float m  = om[(18 + kk) * HWSZ + p];

    float py = dy + (float)(kk / 3) + (float)(ho - 1);
    float px = dx + (float)(kk % 3) + (float)(wo - 1);
    float y0f = floorf(py), x0f = floorf(px);
    float ly = py - y0f, lx = px - x0f;
    int y0 = (int)y0f, x0 = (int)x0f;
    int y1 = y0 + 1,  x1 = x0 + 1;

    float vy0 = ((unsigned)y0 < 64u) ? 1.f : 0.f;
    float vy1 = ((unsigned)y1 < 64u) ? 1.f : 0.f;
    float vx0 = ((unsigned)x0 < 64u) ? 1.f : 0.f;
    float vx1 = ((unsigned)x1 < 64u) ? 1.f : 0.f;

    float w00 = (1.f - ly) * (1.f - lx) * vy0 * vx0 * m;
    float w01 = (1.f - ly) * lx         * vy0 * vx1 * m;
    float w10 = ly         * (1.f - lx) * vy1 * vx0 * m;
    float w11 = ly         * lx         * vy1 * vx1 * m;

    int iy0 = min(max(y0, 0), 63), iy1 = min(max(y1, 0), 63);
    int ix0 = min(max(x0, 0), 63), ix1 = min(max(x1, 0), 63);
    int i00 = iy0 * WW + ix0, i01 = iy0 * WW + ix1;
    int i10 = iy1 * WW + ix0, i11 = iy1 * WW + ix1;

    const float* xb = x + (size_t)b * C1 * HWSZ;
    float* cb = g_col + ((size_t)b * CK + kk) * HWSZ + p;

#pragma unroll 4
    for (int c = 0; c < C1; c++) {
        const float* xc = xb + (size_t)c * HWSZ;
        float v = w00 * __ldg(xc + i00) + w01 * __ldg(xc + i01)
                + w10 * __ldg(xc + i10) + w11 * __ldg(xc + i11);
        cb[(size_t)c * KK * HWSZ] = v;
    }
}

// ---------------------------------------------------------------------------
// Kernel 3: batched SGEMM  C[b] = A[256,2304] x col[b][2304,4096]
// BM=BN=128, BK=16, 256 threads, 8x8 microtile, DOUBLE-BUFFERED smem
// (one __syncthreads per k-tile; STS of tile i+1 overlaps FFMA of tile i).
// ---------------------------------------------------------------------------
__global__ __launch_bounds__(256) void gemm_kernel(
    const float* __restrict__ A, float* __restrict__ C)
{
    __shared__ float As[2][16][128];
    __shared__ float Bs[2][16][128];

    const int b  = blockIdx.z;
    const float* Bb = g_col + (size_t)b * CK * HWSZ;
    float* Cb = C + (size_t)b * C2 * HWSZ;
    const int m0 = blockIdx.y * 128, n0 = blockIdx.x * 128;
    const int tid = threadIdx.x;
    const int tx = tid & 15, ty = tid >> 4;

    float acc[2][2][4][4] = {};

    const int aRow = tid >> 1;          // 0..127
    const int aK   = (tid & 1) * 8;     // 0 or 8
    const int bK   = tid >> 5;          // 0..7
    const int bN   = (tid & 31) * 4;

    const float* apBase = A + (size_t)(m0 + aRow) * CK + aK;
    const float* bpBase = Bb + (size_t)bK * HWSZ + n0 + bN;

    // ---- preload tile 0 into buffer 0 ----
    {
        float4 a0 = *(const float4*)(apBase);
        float4 a1 = *(const float4*)(apBase + 4);
        float4 b0 = *(const float4*)(bpBase);
        float4 b1 = *(const float4*)(bpBase + 8 * HWSZ);
        As[0][aK + 0][aRow] = a0.x; As[0][aK + 1][aRow] = a0.y;
        As[0][aK + 2][aRow] = a0.z; As[0][aK + 3][aRow] = a0.w;
        As[0][aK + 4][aRow] = a1.x; As[0][aK + 5][aRow] = a1.y;
        As[0][aK + 6][aRow] = a1.z; As[0][aK + 7][aRow] = a1.w;
        *(float4*)&Bs[0][bK][bN]     = b0;
        *(float4*)&Bs[0][bK + 8][bN] = b1;
    }
    __syncthreads();

    int buf = 0;
    for (int k0 = 16; k0 <= CK; k0 += 16) {
        float4 a0, a1, b0, b1;
        const bool more = (k0 < CK);
        if (more) {
            a0 = *(const float4*)(apBase + k0);
            a1 = *(const float4*)(apBase + k0 + 4);
            b0 = *(const float4*)(bpBase + (size_t)k0 * HWSZ);
            b1 = *(const float4*)(bpBase + (size_t)(k0 + 8) * HWSZ);
        }

#pragma unroll
        for (int k = 0; k < 16; k++) {
            float4 ra0 = *(const float4*)&As[buf][k][ty * 4];
            float4 ra1 = *(const float4*)&As[buf][k][ty * 4 + 64];
            float4 rb0 = *(const float4*)&Bs[buf][k][tx * 4];
            float4 rb1 = *(const float4*)&Bs[buf][k][tx * 4 + 64];
            float ra[2][4] = {{ra0.x, ra0.y, ra0.z, ra0.w},
                              {ra1.x, ra1.y, ra1.z, ra1.w}};
            float rb[2][4] = {{rb0.x, rb0.y, rb0.z, rb0.w},
                              {rb1.x, rb1.y, rb1.z, rb1.w}};
#pragma unroll
            for (int rm = 0; rm < 2; rm++)
#pragma unroll
                for (int cn = 0; cn < 2; cn++)
#pragma unroll
                    for (int i = 0; i < 4; i++)
#pragma unroll
                        for (int j = 0; j < 4; j++)
                            acc[rm][cn][i][j] = fmaf(ra[rm][i], rb[cn][j],
                                                     acc[rm][cn][i][j]);
        }

        if (more) {
            int nb = buf ^ 1;
            As[nb][aK + 0][aRow] = a0.x; As[nb][aK + 1][aRow] = a0.y;
            As[nb][aK + 2][aRow] = a0.z; As[nb][aK + 3][aRow] = a0.w;
            As[nb][aK + 4][aRow] = a1.x; As[nb][aK + 5][aRow] = a1.y;
            As[nb][aK + 6][aRow] = a1.z; As[nb][aK + 7][aRow] = a1.w;
            *(float4*)&Bs[nb][bK][bN]     = b0;
            *(float4*)&Bs[nb][bK + 8][bN] = b1;
            __syncthreads();
            buf = nb;
        }
    }

    // store 8x8 microtile as float4s
#pragma unroll
    for (int rm = 0; rm < 2; rm++) {
#pragma unroll
        for (int i = 0; i < 4; i++) {
            int row = m0 + ty * 4 + rm * 64 + i;
#pragma unroll
            for (int cn = 0; cn < 2; cn++) {
                int colx = n0 + tx * 4 + cn * 64;
                float4 v = make_float4(acc[rm][cn][i][0], acc[rm][cn][i][1],
                                       acc[rm][cn][i][2], acc[rm][cn][i][3]);
                *(float4*)&Cb[(size_t)row * HWSZ + colx] = v;
            }
        }
    }
}

// ---------------------------------------------------------------------------
extern "C" void kernel_launch(void* const* d_in, const int* in_sizes, int n_in,
                              void* d_out, int out_size)
{
    const float* x  = (const float*)d_in[0];
    const float* ow = (const float*)d_in[1];
    const float* ob = (const float*)d_in[2];
    const float* mw = (const float*)d_in[3];
    const float* mb = (const float*)d_in[4];
    const float* rw = (const float*)d_in[5];
    float* out = (float*)d_out;

    // Stage 1: offset/modulator conv  -> g_offmod
    {
        dim3 grid(4, 4, NB);
        dim3 block(16, 16);
        offmod_kernel<<<grid, block>>>(x, ow, ob, mw, mb);
    }
    // Stage 2: bilinear sampling -> g_col
    {
        int total = NB * KK * HWSZ;        // 294912
        sample_kernel<<<total / 256, 256>>>(x);
    }
    // Stage 3: batched GEMM -> out
    {
        dim3 grid(HWSZ / 128, C2 / 128, NB);   // (32, 2, 8)
        gemm_kernel<<<grid, 256>>>(rw, out);
    }
}

// round 14
// speedup vs baseline: 1.5257x; 1.5257x over previous
#include <cuda_runtime.h>
#include <cuda_bf16.h>
#include <cstdint>

#define HH 64
#define WW 64
#define NB 8
#define C1 256
#define C2 256
#define KK 9
#define HWSZ 4096
#define CK 2304  /* C1*KK */

// Scratch (allocation-free rule: __device__ globals)
__device__ float g_offmod[NB * 27 * HWSZ];          // 3.5 MB
__device__ float g_col[(size_t)NB * CK * HWSZ];     // 302 MB im2col tensor (fp32)
__device__ float g_part[NB * 4 * 27 * HWSZ];        // 14 MB split-K partials

// ===========================================================================
// helpers
// ===========================================================================
__device__ __forceinline__ uint32_t smem_u32(const void* p) {
    uint32_t a;
    asm("{ .reg .u64 t; cvta.to.shared.u64 t, %1; cvt.u32.u64 %0, t; }" : "=r"(a) : "l"(p));
    return a;
}
__device__ __forceinline__ void ldsm_x4(uint32_t& r0, uint32_t& r1, uint32_t& r2,
                                        uint32_t& r3, uint32_t addr) {
    asm volatile("ldmatrix.sync.aligned.m8n8.x4.shared.b16 {%0,%1,%2,%3}, [%4];"
                 : "=r"(r0), "=r"(r1), "=r"(r2), "=r"(r3) : "r"(addr));
}
__device__ __forceinline__ void ldsm_x4t(uint32_t& r0, uint32_t& r1, uint32_t& r2,
                                         uint32_t& r3, uint32_t addr) {
    asm volatile("ldmatrix.sync.aligned.m8n8.x4.trans.shared.b16 {%0,%1,%2,%3}, [%4];"
                 : "=r"(r0), "=r"(r1), "=r"(r2), "=r"(r3) : "r"(addr));
}
__device__ __forceinline__ void mma16816(float* c, uint32_t a0, uint32_t a1,
                                         uint32_t a2, uint32_t a3,
                                         uint32_t b0, uint32_t b1) {
    asm volatile(
        "mma.sync.aligned.m16n8k16.row.col.f32.bf16.bf16.f32 "
        "{%0,%1,%2,%3}, {%4,%5,%6,%7}, {%8,%9}, {%0,%1,%2,%3};"
        : "+f"(c[0]), "+f"(c[1]), "+f"(c[2]), "+f"(c[3])
        : "r"(a0), "r"(a1), "r"(a2), "r"(a3), "r"(b0), "r"(b1));
}
__device__ __forceinline__ void split_bf16(float v, __nv_bfloat16& h, __nv_bfloat16& l) {
    h = __float2bfloat16(v);
    l = __float2bfloat16(v - __bfloat162float(h));
}
__device__ __forceinline__ uint32_t pk(__nv_bfloat16 a, __nv_bfloat16 b) {
    uint16_t ua = *(uint16_t*)&a, ub = *(uint16_t*)&b;
    return (uint32_t)ua | ((uint32_t)ub << 16);
}

// ===========================================================================
// Kernel 1a: offset/modulator conv, split-K over channels (4 chunks of 64).
// ===========================================================================
#define CH 8
__global__ __launch_bounds__(256) void offmod_part_kernel(
    const float* __restrict__ x,
    const float* __restrict__ ow, const float* __restrict__ mw)
{
    __shared__ float sx[CH][18 * 18];
    __shared__ float sw[27][CH * 9];
    const int b     = blockIdx.z >> 2;
    const int chunk = blockIdx.z & 3;
    const int ty0 = blockIdx.y * 16, tx0 = blockIdx.x * 16;
    const int tx  = threadIdx.x, ty = threadIdx.y;
    const int tid = ty * 16 + tx;

    float acc[27];
#pragma unroll
    for (int i = 0; i < 27; i++) acc[i] = 0.f;

    const int cBeg = chunk * 64;
    for (int c0 = cBeg; c0 < cBeg + 64; c0 += CH) {
        __syncthreads();
        for (int i = tid; i < CH * 324; i += 256) {
            int c = i / 324, r = i % 324;
            int yy = r / 18 - 1 + ty0;
            int xx = r % 18 - 1 + tx0;
            float v = 0.f;
            if ((unsigned)yy < 64u && (unsigned)xx < 64u)
                v = x[(((b * C1) + c0 + c) * HH + yy) * WW + xx];
            sx[c][r] = v;
        }
        for (int i = tid; i < 27 * CH * 9; i += 256) {
            int oc = i / (CH * 9), r = i % (CH * 9);
            int c = r / 9, k = r % 9;
            sw[oc][r] = (oc < 18) ? ow[(oc * C1 + c0 + c) * 9 + k]
                                  : mw[((oc - 18) * C1 + c0 + c) * 9 + k];
        }
        __syncthreads();
#pragma unroll
        for (int c = 0; c < CH; c++) {
            float xv[9];
#pragma unroll
            for (int k = 0; k < 9; k++)
                xv[k] = sx[c][(ty + k / 3) * 18 + (tx + k % 3)];
#pragma unroll
            for (int oc = 0; oc < 27; oc++) {
#pragma unroll
                for (int k = 0; k < 9; k++)
                    acc[oc] = fmaf(xv[k], sw[oc][c * 9 + k], acc[oc]);
            }
        }
    }

    const int p = (ty0 + ty) * WW + (tx0 + tx);
#pragma unroll
    for (int oc = 0; oc < 27; oc++)
        g_part[((b * 4 + chunk) * 27 + oc) * HWSZ + p] = acc[oc];
}

// Kernel 1b: reduce + bias + clip/sigmoid
__global__ __launch_bounds__(256) void offmod_reduce_kernel(
    const float* __restrict__ ob, const float* __restrict__ mb)
{
    int t = blockIdx.x * 256 + threadIdx.x;
    int b = t >> 12, p = t & 4095;
#pragma unroll
    for (int oc = 0; oc < 27; oc++) {
        float s = (oc < 18) ? ob[oc] : mb[oc - 18];
#pragma unroll
        for (int ch = 0; ch < 4; ch++)
            s += g_part[((b * 4 + ch) * 27 + oc) * HWSZ + p];
        if (oc < 18) s = fminf(fmaxf(s, -16.f), 16.f);
        else         s = 1.f / (1.f + expf(-s));
        g_offmod[(b * 27 + oc) * HWSZ + p] = s;
    }
}

// ===========================================================================
// Kernel 2: bilinear sampling + modulation -> g_col  (verified)
// ===========================================================================
__global__ __launch_bounds__(256) void sample_kernel(const float* __restrict__ x)
{
    int t  = blockIdx.x * 256 + threadIdx.x;
    int wo = t & 63;
    int ho = (t >> 6) & 63;
    int r  = t >> 12;
    int kk = r % 9;
    int b  = r / 9;
    int p  = ho * WW + wo;

    const float* om = g_offmod + b * 27 * HWSZ;
    float dy = om[(2 * kk) * HWSZ + p];
    float dx = om[(2 * kk + 1) * HWSZ + p];
    float m  = om[(18 + kk) * HWSZ + p];

    float py = dy + (float)(kk / 3) + (float)(ho - 1);
    float px = dx + (float)(kk % 3) + (float)(wo - 1);
    float y0f = floorf(py), x0f = floorf(px);
    float ly = py - y0f, lx = px - x0f;
    int y0 = (int)y0f, x0 = (int)x0f;
    int y1 = y0 + 1,  x1 = x0 + 1;

    float vy0 = ((unsigned)y0 < 64u) ? 1.f : 0.f;
    float vy1 = ((unsigned)y1 < 64u) ? 1.f : 0.f;
    float vx0 = ((unsigned)x0 < 64u) ? 1.f : 0.f;
    float vx1 = ((unsigned)x1 < 64u) ? 1.f : 0.f;

    float w00 = (1.f - ly) * (1.f - lx) * vy0 * vx0 * m;
    float w01 = (1.f - ly) * lx         * vy0 * vx1 * m;
    float w10 = ly         * (1.f - lx) * vy1 * vx0 * m;
    float w11 = ly         * lx         * vy1 * vx1 * m;

    int iy0 = min(max(y0, 0), 63), iy1 = min(max(y1, 0), 63);
    int ix0 = min(max(x0, 0), 63), ix1 = min(max(x1, 0), 63);
    int i00 = iy0 * WW + ix0, i01 = iy0 * WW + ix1;
    int i10 = iy1 * WW + ix0, i11 = iy1 * WW + ix1;

    const float* xb = x + (size_t)b * C1 * HWSZ;
    float* cb = g_col + ((size_t)b * CK + kk) * HWSZ + p;

#pragma unroll 4
    for (int c = 0; c < C1; c++) {
        const float* xc = xb + (size_t)c * HWSZ;
        float v = w00 * __ldg(xc + i00) + w01 * __ldg(xc + i01)
                + w10 * __ldg(xc + i10) + w11 * __ldg(xc + i11);
        cb[(size_t)c * KK * HWSZ] = v;
    }
}

// ===========================================================================
// Kernel 3: bf16-split GEMM via mma.sync.m16n8k16 (HMMA; compute_103-safe).
// C[128,128] tile/CTA. 8 warps (2m x 4n), warp tile 64x32. KT=32.
// A smem [m][k] stride 40 halves (ldmatrix, conflict-free).
// B smem [k][n] stride 136 halves (ldmatrix.trans, conflict-free, vector STS).
// 3-term split: ah*bh + ah*bl + al*bh.
// ===========================================================================
#define KT 32
#define LDA 40                 /* halves */
#define LDB 136                /* halves */
#define A_TILE (128 * LDA * 2) /* 10240 B */
#define B_TILE (KT * LDB * 2)  /*  8704 B */
#define OFF_AH 0
#define OFF_AL (A_TILE)
#define OFF_BH (2 * A_TILE)
#define OFF_BL (2 * A_TILE + B_TILE)
#define BUFSTRIDE (2 * A_TILE + 2 * B_TILE)   /* 37888 B */
#define GEMM_SMEM (2 * BUFSTRIDE)             /* 75776 B */

__global__ __launch_bounds__(256) void gemm_mma_kernel(
    const float* __restrict__ A, float* __restrict__ C)
{
    extern __shared__ char dsm[];
    const int tid  = threadIdx.x;
    const int wid  = tid >> 5;
    const int lane = tid & 31;
    const int wm = (wid >> 2) * 64;   // warp m base in tile
    const int wn = (wid & 3) * 32;    // warp n base in tile

    const int m0 = blockIdx.y * 128, n0 = blockIdx.x * 128;
    const float* Bp = g_col + (size_t)blockIdx.z * CK * HWSZ;
    float* Co = C + (size_t)blockIdx.z * C2 * HWSZ;
    const uint32_t sbase = smem_u32(dsm);

    float acc[4][4][4];
#pragma unroll
    for (int i = 0; i < 4; i++)
#pragma unroll
        for (int j = 0; j < 4; j++)
#pragma unroll
            for (int e = 0; e < 4; e++) acc[i][j][e] = 0.f;

    float4 pa[4], pb[4];
    // preload tile 0
#pragma unroll
    for (int j = 0; j < 4; j++) {
        int idx = j * 256 + tid;
        int ar = idx >> 3, aq = (idx & 7) << 2;
        pa[j] = *(const float4*)(A + (size_t)(m0 + ar) * CK + aq);
        int bk = idx >> 5, bn = (idx & 31) << 2;
        pb[j] = *(const float4*)(Bp + (size_t)bk * HWSZ + n0 + bn);
    }

    const int NT = CK / KT;   // 72
    for (int t = 0; t < NT; t++) {
        const int buf = t & 1;
        char* sb = dsm + buf * BUFSTRIDE;

        // ---- convert + STS current tile ----
#pragma unroll
        for (int j = 0; j < 4; j++) {
            int idx = j * 256 + tid;
            {   // A: [m][k], 4 halves along k
                int ar = idx >> 3, aq = (idx & 7) << 2;
                __nv_bfloat16 h0, h1, h2, h3, l0, l1, l2, l3;
                split_bf16(pa[j].x, h0, l0); split_bf16(pa[j].y, h1, l1);
                split_bf16(pa[j].z, h2, l2); split_bf16(pa[j].w, h3, l3);
                uint32_t off = (uint32_t)(ar * LDA + aq) * 2;
                *(uint2*)(sb + OFF_AH + off) = make_uint2(pk(h0, h1), pk(h2, h3));
                *(uint2*)(sb + OFF_AL + off) = make_uint2(pk(l0, l1), pk(l2, l3));
            }
            {   // B: [k][n], 4 halves along n (contiguous vector STS)
                int bk = idx >> 5, bn = (idx & 31) << 2;
                __nv_bfloat16 h0, h1, h2, h3, l0, l1, l2, l3;
                split_bf16(pb[j].x, h0, l0); split_bf16(pb[j].y, h1, l1);
                split_bf16(pb[j].z, h2, l2); split_bf16(pb[j].w, h3, l3);
                uint32_t off = (uint32_t)(bk * LDB + bn) * 2;
                *(uint2*)(sb + OFF_BH + off) = make_uint2(pk(h0, h1), pk(h2, h3));
                *(uint2*)(sb + OFF_BL + off) = make_uint2(pk(l0, l1), pk(l2, l3));
            }
        }
        // ---- prefetch next tile into regs (overlaps compute) ----
        if (t + 1 < NT) {
            const int k0n = (t + 1) * KT;
#pragma unroll
            for (int j = 0; j < 4; j++) {
                int idx = j * 256 + tid;
                int ar = idx >> 3, aq = (idx & 7) << 2;
                pa[j] = *(const float4*)(A + (size_t)(m0 + ar) * CK + k0n + aq);
                int bk = idx >> 5, bn = (idx & 31) << 2;
                pb[j] = *(const float4*)(Bp + (size_t)(k0n + bk) * HWSZ + n0 + bn);
            }
        }
        __syncthreads();

        // ---- compute from smem buf ----
        const uint32_t sA = sbase + buf * BUFSTRIDE;
#pragma unroll
        for (int k16 = 0; k16 < 2; k16++) {
            uint32_t ah[4][4], al[4][4], bh[2][4], bl[2][4];
            // A frags: row = wm + mi*16 + (lane&15), kh = k16*16 + (lane>>4)*8
            const uint32_t arow = (uint32_t)(lane & 15);
            const uint32_t akh  = (uint32_t)(k16 * 16 + (lane >> 4) * 8);
#pragma unroll
            for (int mi = 0; mi < 4; mi++) {
                uint32_t off = ((wm + mi * 16 + arow) * LDA + akh) * 2;
                ldsm_x4(ah[mi][0], ah[mi][1], ah[mi][2], ah[mi][3], sA + OFF_AH + off);
                ldsm_x4(al[mi][0], al[mi][1], al[mi][2], al[mi][3], sA + OFF_AL + off);
            }
            // B frags (trans): krow = k16*16 + ((lane>>3)&1)*8 + (lane&7)
            //                  ncol = wn + nf2*16 + (lane>>4)*8
            const uint32_t bkr = (uint32_t)(k16 * 16 + ((lane >> 3) & 1) * 8 + (lane & 7));
            const uint32_t bnc = (uint32_t)((lane >> 4) * 8);
#pragma unroll
            for (int nf2 = 0; nf2 < 2; nf2++) {
                uint32_t off = (bkr * LDB + wn + nf2 * 16 + bnc) * 2;
                ldsm_x4t(bh[nf2][0], bh[nf2][1], bh[nf2][2], bh[nf2][3], sA + OFF_BH + off);
                ldsm_x4t(bl[nf2][0], bl[nf2][1], bl[nf2][2], bl[nf2][3], sA + OFF_BL + off);
            }
#pragma unroll
            for (int mi = 0; mi < 4; mi++) {
#pragma unroll
                for (int nf = 0; nf < 4; nf++) {
                    int g = nf >> 1, r = (nf & 1) * 2;
                    mma16816(acc[mi][nf], ah[mi][0], ah[mi][1], ah[mi][2], ah[mi][3],
                             bh[g][r], bh[g][r + 1]);
                    mma16816(acc[mi][nf], ah[mi][0], ah[mi][1], ah[mi][2], ah[mi][3],
                             bl[g][r], bl[g][r + 1]);
                    mma16816(acc[mi][nf], al[mi][0], al[mi][1], al[mi][2], al[mi][3],
                             bh[g][r], bh[g][r + 1]);
                }
            }
        }
        __syncthreads();
    }

    // ---- epilogue: direct STG (float2 per half-frag) ----
#pragma unroll
    for (int mi = 0; mi < 4; mi++) {
#pragma unroll
        for (int nf = 0; nf < 4; nf++) {
            int row = m0 + wm + mi * 16 + (lane >> 2);
            int col = n0 + wn + nf * 8 + (lane & 3) * 2;
            *(float2*)(Co + (size_t)row * HWSZ + col) =
                make_float2(acc[mi][nf][0], acc[mi][nf][1]);
            *(float2*)(Co + (size_t)(row + 8) * HWSZ + col) =
                make_float2(acc[mi][nf][2], acc[mi][nf][3]);
        }
    }
}

// ---------------------------------------------------------------------------
extern "C" void kernel_launch(void* const* d_in, const int* in_sizes, int n_in,
                              void* d_out, int out_size)
{
    const float* x  = (const float*)d_in[0];
    const float* ow = (const float*)d_in[1];
    const float* ob = (const float*)d_in[2];
    const float* mw = (const float*)d_in[3];
    const float* mb = (const float*)d_in[4];
    const float* rw = (const float*)d_in[5];
    float* out = (float*)d_out;

    cudaFuncSetAttribute(gemm_mma_kernel,
                         cudaFuncAttributeMaxDynamicSharedMemorySize, GEMM_SMEM);

    // Stage 1: offset/modulator conv (split-K) + reduce
    {
        dim3 grid(4, 4, NB * 4);
        dim3 block(16, 16);
        offmod_part_kernel<<<grid, block>>>(x, ow, mw);
        offmod_reduce_kernel<<<128, 256>>>(ob, mb);
    }
    // Stage 2: bilinear sampling -> g_col
    {
        int total = NB * KK * HWSZ;            // 294912
        sample_kernel<<<total / 256, 256>>>(x);
    }
    // Stage 3: bf16-split HMMA GEMM -> out
    {
        dim3 grid(HWSZ / 128, C2 / 128, NB);   // (32, 2, 8)
        gemm_mma_kernel<<<grid, 256, GEMM_SMEM>>>(rw, out);
    }
}